// round 4
// baseline (speedup 1.0000x reference)
#include <cuda_runtime.h>
#include <math.h>

#define T_TOK 1024
#define H_DIM 2048
#define I_DIM 768
#define E_NUM 32
#define K_TOP 8

#define BM 128
#define BN 64
#define BK 32
#define RS 40            // smem row stride in words (== 8 mod 32 -> conflict-free frags)

#define GU_SLAB ((BM + BN + BN) * RS)   // 10240 words per buffer
#define DN_SLAB ((BM + BN) * RS)        // 7680 words per buffer

// ---------------- scratch ----------------
__device__ int   g_cnt[E_NUM];
__device__ int   g_off[E_NUM + 1];
__device__ int   g_list_tok[E_NUM * T_TOK];
__device__ float g_list_w[E_NUM * T_TOK];
__device__ int   g_list_tk[E_NUM * T_TOK];
__device__ int   g_slot_of[T_TOK * K_TOP];
__device__ float g_act[(size_t)T_TOK * K_TOP * I_DIM];
__device__ float g_pair[(size_t)T_TOK * K_TOP * H_DIM];

__global__ void zero_cnt_kernel() {
    if (threadIdx.x < E_NUM) g_cnt[threadIdx.x] = 0;
}

// ---------------- router ----------------
__global__ void router_kernel(const float* __restrict__ x,
                              const float* __restrict__ gate_w,
                              float* __restrict__ logits_out) {
    const int TPB = 4;
    __shared__ float xs[TPB][H_DIM];
    __shared__ float lg[TPB][E_NUM];

    int t0 = blockIdx.x * TPB;
    const float4* xv  = (const float4*)(x + (size_t)t0 * H_DIM);
    float4*       xsv = (float4*)&xs[0][0];
    for (int i = threadIdx.x; i < TPB * H_DIM / 4; i += blockDim.x) xsv[i] = xv[i];
    __syncthreads();

    int warp = threadIdx.x >> 5;
    int lane = threadIdx.x & 31;

    for (int sub = 0; sub < 4; sub++) {
        int e = warp + sub * 8;
        const float* w = gate_w + (size_t)e * H_DIM;
        float p0 = 0.f, p1 = 0.f, p2 = 0.f, p3 = 0.f;
        for (int h = lane; h < H_DIM; h += 32) {
            float wv = w[h];
            p0 += xs[0][h] * wv;
            p1 += xs[1][h] * wv;
            p2 += xs[2][h] * wv;
            p3 += xs[3][h] * wv;
        }
        for (int o = 16; o; o >>= 1) {
            p0 += __shfl_xor_sync(0xFFFFFFFFu, p0, o);
            p1 += __shfl_xor_sync(0xFFFFFFFFu, p1, o);
            p2 += __shfl_xor_sync(0xFFFFFFFFu, p2, o);
            p3 += __shfl_xor_sync(0xFFFFFFFFu, p3, o);
        }
        if (lane == 0) { lg[0][e] = p0; lg[1][e] = p1; lg[2][e] = p2; lg[3][e] = p3; }
    }
    __syncthreads();

    if (warp < TPB) {
        int t = t0 + warp;
        float logit = lg[warp][lane];
        if (logits_out) logits_out[(size_t)t * E_NUM + lane] = logit;

        float m = logit;
        for (int o = 16; o; o >>= 1) m = fmaxf(m, __shfl_xor_sync(0xFFFFFFFFu, m, o));
        float ex = expf(logit - m);
        float s = ex;
        for (int o = 16; o; o >>= 1) s += __shfl_xor_sync(0xFFFFFFFFu, s, o);
        float prob = ex / s;

        float v = prob;
        float wsum = 0.f;
        float selw[K_TOP];
        int   sele[K_TOP];
#pragma unroll
        for (int k = 0; k < K_TOP; k++) {
            float mv = v;
            for (int o = 16; o; o >>= 1) mv = fmaxf(mv, __shfl_xor_sync(0xFFFFFFFFu, mv, o));
            unsigned msk = __ballot_sync(0xFFFFFFFFu, v == mv);
            int src = __ffs(msk) - 1;
            if (lane == 0) { sele[k] = src; selw[k] = mv; wsum += mv; }
            if (lane == src) v = -1.f;
        }
        if (lane == 0) {
#pragma unroll
            for (int k = 0; k < K_TOP; k++) {
                int e = sele[k];
                float wn = selw[k] / wsum;
                int pos = atomicAdd(&g_cnt[e], 1);
                g_list_tok[e * T_TOK + pos] = t;
                g_list_w[e * T_TOK + pos]   = wn;
                g_list_tk[e * T_TOK + pos]  = t * K_TOP + k;
            }
        }
    }
}

__global__ void scan_kernel() {
    if (threadIdx.x == 0) {
        int acc = 0;
        for (int e = 0; e < E_NUM; e++) { g_off[e] = acc; acc += g_cnt[e]; }
        g_off[E_NUM] = acc;
    }
}

__global__ void remap_kernel() {
    int e = blockIdx.x;
    int n = g_cnt[e], o = g_off[e];
    for (int p = threadIdx.x; p < n; p += blockDim.x)
        g_slot_of[g_list_tk[e * T_TOK + p]] = o + p;
}

__device__ __forceinline__ float silu_f(float g) { return g / (1.f + expf(-g)); }

__device__ __forceinline__ unsigned f2tf(float f) {
    unsigned r;
    asm("cvt.rna.tf32.f32 %0, %1;" : "=r"(r) : "f"(f));
    return r;
}
__device__ __forceinline__ void mma_tf32(float* c, unsigned a0, unsigned a1, unsigned a2, unsigned a3,
                                         unsigned b0, unsigned b1) {
    asm volatile("mma.sync.aligned.m16n8k8.row.col.f32.tf32.tf32.f32 "
                 "{%0,%1,%2,%3}, {%4,%5,%6,%7}, {%8,%9}, {%0,%1,%2,%3};"
                 : "+f"(c[0]), "+f"(c[1]), "+f"(c[2]), "+f"(c[3])
                 : "r"(a0), "r"(a1), "r"(a2), "r"(a3), "r"(b0), "r"(b1));
}

// store an 8-k-wide chunk (two float4: a = k[0..3], b = k[4..7]) into permuted smem row
__device__ __forceinline__ void st_chunk(unsigned* row_base, int kg, float4 a, float4 b) {
    unsigned w[8];
    w[0] = f2tf(a.x); w[1] = f2tf(b.x); w[2] = f2tf(a.y); w[3] = f2tf(b.y);
    w[4] = f2tf(a.z); w[5] = f2tf(b.z); w[6] = f2tf(a.w); w[7] = f2tf(b.w);
    *(uint4*)(row_base + kg * 8)     = *(uint4*)w;
    *(uint4*)(row_base + kg * 8 + 4) = *(uint4*)(w + 4);
}

extern __shared__ unsigned smem_u[];

// ---------------- grouped gate+up GEMM (tf32 mma, double-buffered) ----------------
__global__ __launch_bounds__(256) void gateup_kernel(const float* __restrict__ x,
                                                     const float* __restrict__ gw,
                                                     const float* __restrict__ uw) {
    int e  = blockIdx.z;
    int n  = g_cnt[e];
    int m0 = blockIdx.x * BM;
    if (m0 >= n) return;
    int c0 = blockIdx.y * BN;

    int tid  = threadIdx.x;
    int lane = tid & 31;
    int warp = tid >> 5;
    int wM = warp & 3;
    int wN = warp >> 2;

    // loader mapping: thread owns rows (lr, lr+64) of A, row lr of Bg/Bu, k-group kg
    int lr = tid >> 2;      // 0..63
    int kg = tid & 3;       // 8-wide k-group within 32-slab

    int tokA0 = g_list_tok[e * T_TOK + min(m0 + lr,      n - 1)];
    int tokA1 = g_list_tok[e * T_TOK + min(m0 + lr + 64, n - 1)];
    const float* pA0 = x  + (size_t)tokA0 * H_DIM + kg * 8;
    const float* pA1 = x  + (size_t)tokA1 * H_DIM + kg * 8;
    const float* pG  = gw + ((size_t)e * I_DIM + (c0 + lr)) * H_DIM + kg * 8;
    const float* pU  = uw + ((size_t)e * I_DIM + (c0 + lr)) * H_DIM + kg * 8;

    float cg[2][4][4] = {};
    float cu[2][4][4] = {};

    float4 rA0a, rA0b, rA1a, rA1b, rGa, rGb, rUa, rUb;

#define GU_LOAD(h0)                                            \
    { rA0a = *(const float4*)(pA0 + (h0));                     \
      rA0b = *(const float4*)(pA0 + (h0) + 4);                 \
      rA1a = *(const float4*)(pA1 + (h0));                     \
      rA1b = *(const float4*)(pA1 + (h0) + 4);                 \
      rGa  = *(const float4*)(pG  + (h0));                     \
      rGb  = *(const float4*)(pG  + (h0) + 4);                 \
      rUa  = *(const float4*)(pU  + (h0));                     \
      rUb  = *(const float4*)(pU  + (h0) + 4); }

#define GU_STORE(buf)                                                          \
    { unsigned* As  = smem_u + (buf) * GU_SLAB;                                \
      unsigned* Bgs = As + BM * RS;                                            \
      unsigned* Bus = Bgs + BN * RS;                                           \
      st_chunk(As  + lr * RS,        kg, rA0a, rA0b);                          \
      st_chunk(As  + (lr + 64) * RS, kg, rA1a, rA1b);                          \
      st_chunk(Bgs + lr * RS,        kg, rGa,  rGb);                           \
      st_chunk(Bus + lr * RS,        kg, rUa,  rUb); }

    int g  = lane >> 2;
    int tq = lane & 3;

    GU_LOAD(0);
    GU_STORE(0);
    __syncthreads();

#pragma unroll 2
    for (int i = 0; i < H_DIM / BK; i++) {
        bool more = (i + 1 < H_DIM / BK);
        if (more) GU_LOAD((i + 1) * BK);

        const unsigned* As  = smem_u + (i & 1) * GU_SLAB;
        const unsigned* Bgs = As + BM * RS;
        const unsigned* Bus = Bgs + BN * RS;
#pragma unroll
        for (int kk = 0; kk < 4; kk++) {
            int kc2 = kk * 8 + tq * 2;
            uint2 aLo[2], aHi[2];
#pragma unroll
            for (int mi = 0; mi < 2; mi++) {
                int r = wM * 32 + mi * 16 + g;
                aLo[mi] = *(const uint2*)&As[r * RS + kc2];        // a0, a2
                aHi[mi] = *(const uint2*)&As[(r + 8) * RS + kc2];  // a1, a3
            }
#pragma unroll
            for (int ni = 0; ni < 4; ni++) {
                int br = wN * 32 + ni * 8 + g;
                uint2 bg = *(const uint2*)&Bgs[br * RS + kc2];
                uint2 bu = *(const uint2*)&Bus[br * RS + kc2];
#pragma unroll
                for (int mi = 0; mi < 2; mi++) {
                    mma_tf32(cg[mi][ni], aLo[mi].x, aHi[mi].x, aLo[mi].y, aHi[mi].y, bg.x, bg.y);
                    mma_tf32(cu[mi][ni], aLo[mi].x, aHi[mi].x, aLo[mi].y, aHi[mi].y, bu.x, bu.y);
                }
            }
        }

        if (more) GU_STORE((i + 1) & 1);
        __syncthreads();
    }

    // ---- epilogue ----
    int off = g_off[e];
#pragma unroll
    for (int mi = 0; mi < 2; mi++) {
        int r0 = m0 + wM * 32 + mi * 16 + g;
        int r1 = r0 + 8;
        float w0 = (r0 < n) ? g_list_w[e * T_TOK + r0] : 0.f;
        float w1 = (r1 < n) ? g_list_w[e * T_TOK + r1] : 0.f;
#pragma unroll
        for (int ni = 0; ni < 4; ni++) {
            int col = c0 + wN * 32 + ni * 8 + 2 * tq;
            if (r0 < n) {
                float2 o;
                o.x = silu_f(cg[mi][ni][0]) * cu[mi][ni][0] * w0;
                o.y = silu_f(cg[mi][ni][1]) * cu[mi][ni][1] * w0;
                *(float2*)&g_act[((size_t)(off + r0)) * I_DIM + col] = o;
            }
            if (r1 < n) {
                float2 o;
                o.x = silu_f(cg[mi][ni][2]) * cu[mi][ni][2] * w1;
                o.y = silu_f(cg[mi][ni][3]) * cu[mi][ni][3] * w1;
                *(float2*)&g_act[((size_t)(off + r1)) * I_DIM + col] = o;
            }
        }
    }
#undef GU_LOAD
#undef GU_STORE
}

// ---------------- grouped down-proj GEMM (tf32 mma, double-buffered) ----------------
__global__ __launch_bounds__(256) void down_kernel(const float* __restrict__ dw) {
    int e  = blockIdx.z;
    int n  = g_cnt[e];
    int m0 = blockIdx.x * BM;
    if (m0 >= n) return;
    int c0  = blockIdx.y * BN;
    int off = g_off[e];

    int tid  = threadIdx.x;
    int lane = tid & 31;
    int warp = tid >> 5;
    int wM = warp & 3;
    int wN = warp >> 2;

    int lr = tid >> 2;
    int kg = tid & 3;

    const float* pA0 = g_act + (size_t)(off + min(m0 + lr,      n - 1)) * I_DIM + kg * 8;
    const float* pA1 = g_act + (size_t)(off + min(m0 + lr + 64, n - 1)) * I_DIM + kg * 8;
    const float* pB  = dw + ((size_t)e * H_DIM + (c0 + lr)) * I_DIM + kg * 8;

    float c[2][4][4] = {};

    float4 rA0a, rA0b, rA1a, rA1b, rBa, rBb;

#define DN_LOAD(k0)                                            \
    { rA0a = *(const float4*)(pA0 + (k0));                     \
      rA0b = *(const float4*)(pA0 + (k0) + 4);                 \
      rA1a = *(const float4*)(pA1 + (k0));                     \
      rA1b = *(const float4*)(pA1 + (k0) + 4);                 \
      rBa  = *(const float4*)(pB  + (k0));                     \
      rBb  = *(const float4*)(pB  + (k0) + 4); }

#define DN_STORE(buf)                                                          \
    { unsigned* As = smem_u + (buf) * DN_SLAB;                                 \
      unsigned* Bs = As + BM * RS;                                             \
      st_chunk(As + lr * RS,        kg, rA0a, rA0b);                           \
      st_chunk(As + (lr + 64) * RS, kg, rA1a, rA1b);                           \
      st_chunk(Bs + lr * RS,        kg, rBa,  rBb); }

    int g  = lane >> 2;
    int tq = lane & 3;

    DN_LOAD(0);
    DN_STORE(0);
    __syncthreads();

#pragma unroll 2
    for (int i = 0; i < I_DIM / BK; i++) {
        bool more = (i + 1 < I_DIM / BK);
        if (more) DN_LOAD((i + 1) * BK);

        const unsigned* As = smem_u + (i & 1) * DN_SLAB;
        const unsigned* Bs = As + BM * RS;
#pragma unroll
        for (int kk = 0; kk < 4; kk++) {
            int kc2 = kk * 8 + tq * 2;
            uint2 aLo[2], aHi[2];
#pragma unroll
            for (int mi = 0; mi < 2; mi++) {
                int r = wM * 32 + mi * 16 + g;
                aLo[mi] = *(const uint2*)&As[r * RS + kc2];
                aHi[mi] = *(const uint2*)&As[(r + 8) * RS + kc2];
            }
#pragma unroll
            for (int ni = 0; ni < 4; ni++) {
                int br = wN * 32 + ni * 8 + g;
                uint2 b = *(const uint2*)&Bs[br * RS + kc2];
#pragma unroll
                for (int mi = 0; mi < 2; mi++)
                    mma_tf32(c[mi][ni], aLo[mi].x, aHi[mi].x, aLo[mi].y, aHi[mi].y, b.x, b.y);
            }
        }

        if (more) DN_STORE((i + 1) & 1);
        __syncthreads();
    }

#pragma unroll
    for (int mi = 0; mi < 2; mi++) {
        int r0 = m0 + wM * 32 + mi * 16 + g;
        int r1 = r0 + 8;
#pragma unroll
        for (int ni = 0; ni < 4; ni++) {
            int col = c0 + wN * 32 + ni * 8 + 2 * tq;
            if (r0 < n) {
                float2 o = make_float2(c[mi][ni][0], c[mi][ni][1]);
                *(float2*)&g_pair[((size_t)(off + r0)) * H_DIM + col] = o;
            }
            if (r1 < n) {
                float2 o = make_float2(c[mi][ni][2], c[mi][ni][3]);
                *(float2*)&g_pair[((size_t)(off + r1)) * H_DIM + col] = o;
            }
        }
    }
#undef DN_LOAD
#undef DN_STORE
}

// ---------------- per-token reduction ----------------
__global__ void reduce_kernel(float* __restrict__ out) {
    int t = blockIdx.x;
    int s[K_TOP];
#pragma unroll
    for (int k = 0; k < K_TOP; k++) s[k] = g_slot_of[t * K_TOP + k];
    const float4* base = (const float4*)g_pair;
    float4* ob = (float4*)(out + (size_t)t * H_DIM);
    for (int i = threadIdx.x; i < H_DIM / 4; i += blockDim.x) {
        float4 acc = make_float4(0.f, 0.f, 0.f, 0.f);
#pragma unroll
        for (int k = 0; k < K_TOP; k++) {
            float4 v = base[(size_t)s[k] * (H_DIM / 4) + i];
            acc.x += v.x; acc.y += v.y; acc.z += v.z; acc.w += v.w;
        }
        ob[i] = acc;
    }
}

// ---------------- launch ----------------
extern "C" void kernel_launch(void* const* d_in, const int* in_sizes, int n_in,
                              void* d_out, int out_size) {
    const float* x      = (const float*)d_in[0];
    const float* gate_w = (const float*)d_in[1];
    const float* gw     = (const float*)d_in[2];
    const float* uw     = (const float*)d_in[3];
    const float* dw     = (const float*)d_in[4];
    float* out = (float*)d_out;

    float* logits = (out_size >= T_TOK * H_DIM + T_TOK * E_NUM) ? (out + (size_t)T_TOK * H_DIM)
                                                                : (float*)0;

    static int smem_set = 0;
    // setting an attribute is idempotent & not a stream op; do it every call
    cudaFuncSetAttribute(gateup_kernel, cudaFuncAttributeMaxDynamicSharedMemorySize,
                         2 * GU_SLAB * 4);
    cudaFuncSetAttribute(down_kernel, cudaFuncAttributeMaxDynamicSharedMemorySize,
                         2 * DN_SLAB * 4);
    (void)smem_set;

    zero_cnt_kernel<<<1, 32>>>();
    router_kernel<<<T_TOK / 4, 256>>>(x, gate_w, logits);
    scan_kernel<<<1, 32>>>();
    remap_kernel<<<E_NUM, 256>>>();
    gateup_kernel<<<dim3(T_TOK / BM, I_DIM / BN, E_NUM), 256, 2 * GU_SLAB * 4>>>(x, gw, uw);
    down_kernel<<<dim3(T_TOK / BM, H_DIM / BN, E_NUM), 256, 2 * DN_SLAB * 4>>>(dw);
    reduce_kernel<<<T_TOK, 256>>>(out);
}

// round 6
// speedup vs baseline: 1.1113x; 1.1113x over previous
#include <cuda_runtime.h>
#include <cuda_fp16.h>
#include <math.h>
#include <stdint.h>

#define T_TOK 1024
#define H_DIM 2048
#define I_DIM 768
#define E_NUM 32
#define K_TOP 8

#define BM 128
#define BN 64
#define BK 32            // halves per slab (64 B of data per row)
#define RSB 80           // smem row stride in BYTES (80*r mod 128 covers all 16B groups)

// ---------------- scratch ----------------
__device__ int    g_cnt[E_NUM];
__device__ int    g_off[E_NUM + 1];
__device__ int    g_list_tok[E_NUM * T_TOK];
__device__ float  g_list_w[E_NUM * T_TOK];
__device__ int    g_list_tk[E_NUM * T_TOK];
__device__ int    g_slot_of[T_TOK * K_TOP];
__device__ __half g_act[(size_t)T_TOK * K_TOP * I_DIM];   // fp16 activations
__device__ float  g_pair[(size_t)T_TOK * K_TOP * H_DIM];

__global__ void zero_cnt_kernel() {
    if (threadIdx.x < E_NUM) g_cnt[threadIdx.x] = 0;
}

// ---------------- router ----------------
__global__ void router_kernel(const float* __restrict__ x,
                              const float* __restrict__ gate_w,
                              float* __restrict__ logits_out) {
    const int TPB = 4;
    __shared__ float xs[TPB][H_DIM];
    __shared__ float lg[TPB][E_NUM];

    int t0 = blockIdx.x * TPB;
    const float4* xv  = (const float4*)(x + (size_t)t0 * H_DIM);
    float4*       xsv = (float4*)&xs[0][0];
    for (int i = threadIdx.x; i < TPB * H_DIM / 4; i += blockDim.x) xsv[i] = xv[i];
    __syncthreads();

    int warp = threadIdx.x >> 5;
    int lane = threadIdx.x & 31;

    for (int sub = 0; sub < 4; sub++) {
        int e = warp + sub * 8;
        const float* w = gate_w + (size_t)e * H_DIM;
        float p0 = 0.f, p1 = 0.f, p2 = 0.f, p3 = 0.f;
        for (int h = lane; h < H_DIM; h += 32) {
            float wv = w[h];
            p0 += xs[0][h] * wv;
            p1 += xs[1][h] * wv;
            p2 += xs[2][h] * wv;
            p3 += xs[3][h] * wv;
        }
        for (int o = 16; o; o >>= 1) {
            p0 += __shfl_xor_sync(0xFFFFFFFFu, p0, o);
            p1 += __shfl_xor_sync(0xFFFFFFFFu, p1, o);
            p2 += __shfl_xor_sync(0xFFFFFFFFu, p2, o);
            p3 += __shfl_xor_sync(0xFFFFFFFFu, p3, o);
        }
        if (lane == 0) { lg[0][e] = p0; lg[1][e] = p1; lg[2][e] = p2; lg[3][e] = p3; }
    }
    __syncthreads();

    if (warp < TPB) {
        int t = t0 + warp;
        float logit = lg[warp][lane];
        if (logits_out) logits_out[(size_t)t * E_NUM + lane] = logit;

        float m = logit;
        for (int o = 16; o; o >>= 1) m = fmaxf(m, __shfl_xor_sync(0xFFFFFFFFu, m, o));
        float ex = expf(logit - m);
        float s = ex;
        for (int o = 16; o; o >>= 1) s += __shfl_xor_sync(0xFFFFFFFFu, s, o);
        float prob = ex / s;

        float v = prob;
        float wsum = 0.f;
        float selw[K_TOP];
        int   sele[K_TOP];
#pragma unroll
        for (int k = 0; k < K_TOP; k++) {
            float mv = v;
            for (int o = 16; o; o >>= 1) mv = fmaxf(mv, __shfl_xor_sync(0xFFFFFFFFu, mv, o));
            unsigned msk = __ballot_sync(0xFFFFFFFFu, v == mv);
            int src = __ffs(msk) - 1;
            if (lane == 0) { sele[k] = src; selw[k] = mv; wsum += mv; }
            if (lane == src) v = -1.f;
        }
        if (lane == 0) {
#pragma unroll
            for (int k = 0; k < K_TOP; k++) {
                int e = sele[k];
                float wn = selw[k] / wsum;
                int pos = atomicAdd(&g_cnt[e], 1);
                g_list_tok[e * T_TOK + pos] = t;
                g_list_w[e * T_TOK + pos]   = wn;
                g_list_tk[e * T_TOK + pos]  = t * K_TOP + k;
            }
        }
    }
}

__global__ void scan_kernel() {
    if (threadIdx.x == 0) {
        int acc = 0;
        for (int e = 0; e < E_NUM; e++) { g_off[e] = acc; acc += g_cnt[e]; }
        g_off[E_NUM] = acc;
    }
}

__global__ void remap_kernel() {
    int e = blockIdx.x;
    int n = g_cnt[e], o = g_off[e];
    for (int p = threadIdx.x; p < n; p += blockDim.x)
        g_slot_of[g_list_tk[e * T_TOK + p]] = o + p;
}

__device__ __forceinline__ float silu_f(float g) { return g / (1.f + expf(-g)); }

__device__ __forceinline__ uint32_t smem_u32(const void* p) {
    uint32_t a;
    asm("{ .reg .u64 t; cvta.to.shared.u64 t, %1; cvt.u32.u64 %0, t; }" : "=r"(a) : "l"(p));
    return a;
}

#define LDM4(r0, r1, r2, r3, addr) \
    asm volatile("ldmatrix.sync.aligned.m8n8.x4.shared.b16 {%0,%1,%2,%3}, [%4];" \
                 : "=r"(r0), "=r"(r1), "=r"(r2), "=r"(r3) : "r"(addr))

__device__ __forceinline__ void mma_f16(float* c, uint32_t a0, uint32_t a1, uint32_t a2, uint32_t a3,
                                        uint32_t b0, uint32_t b1) {
    asm volatile("mma.sync.aligned.m16n8k16.row.col.f32.f16.f16.f32 "
                 "{%0,%1,%2,%3}, {%4,%5,%6,%7}, {%8,%9}, {%0,%1,%2,%3};"
                 : "+f"(c[0]), "+f"(c[1]), "+f"(c[2]), "+f"(c[3])
                 : "r"(a0), "r"(a1), "r"(a2), "r"(a3), "r"(b0), "r"(b1));
}

// pack 16 floats (4 float4) -> 8 half2 -> two uint4
__device__ __forceinline__ void pack16(uint4* d, float4 v0, float4 v1, float4 v2, float4 v3) {
    __half2 h[8];
    h[0] = __floats2half2_rn(v0.x, v0.y); h[1] = __floats2half2_rn(v0.z, v0.w);
    h[2] = __floats2half2_rn(v1.x, v1.y); h[3] = __floats2half2_rn(v1.z, v1.w);
    h[4] = __floats2half2_rn(v2.x, v2.y); h[5] = __floats2half2_rn(v2.z, v2.w);
    h[6] = __floats2half2_rn(v3.x, v3.y); h[7] = __floats2half2_rn(v3.z, v3.w);
    d[0] = *(uint4*)&h[0];
    d[1] = *(uint4*)&h[4];
}

// ---------------- grouped gate+up GEMM (fp16 mma m16n8k16) ----------------
__global__ __launch_bounds__(256) void gateup_kernel(const float* __restrict__ x,
                                                     const float* __restrict__ gw,
                                                     const float* __restrict__ uw) {
    int e  = blockIdx.z;
    int n  = g_cnt[e];
    int m0 = blockIdx.x * BM;
    if (m0 >= n) return;
    int c0 = blockIdx.y * BN;

    // smem: A 128 rows, Bg 64 rows, Bu 64 rows, RSB bytes each
    __shared__ __align__(16) unsigned char sm[(BM + BN + BN) * RSB];
    const uint32_t OFF_BG = BM * RSB;
    const uint32_t OFF_BU = (BM + BN) * RSB;
    uint32_t sbase = smem_u32(sm);

    int tid  = threadIdx.x;
    int lane = tid & 31;
    int warp = tid >> 5;
    int wM = warp & 3;      // 32 rows each
    int wN = warp >> 2;     // 32 cols each

    // ---- loader mapping: 2 threads per row ----
    int lr = tid >> 1;      // 0..127
    int hf = tid & 1;       // half of row (16 floats)
    int tokA = g_list_tok[e * T_TOK + min(m0 + lr, n - 1)];
    const float* pA = x + (size_t)tokA * H_DIM + hf * 16;
    uint32_t soA = lr * RSB + hf * 32;
    const float* pB;
    uint32_t soB;
    if (lr < 64) { pB = gw + ((size_t)e * I_DIM + (c0 + lr)) * H_DIM + hf * 16;      soB = OFF_BG + lr * RSB + hf * 32; }
    else         { pB = uw + ((size_t)e * I_DIM + (c0 + lr - 64)) * H_DIM + hf * 16; soB = OFF_BU + (lr - 64) * RSB + hf * 32; }

    // ---- ldmatrix per-lane base addresses ----
    int mat = lane >> 3, rr = lane & 7;
    uint32_t aBase[2], bgBase[2], buBase[2];
#pragma unroll
    for (int mi = 0; mi < 2; mi++)
        aBase[mi] = sbase + (uint32_t)((wM * 32 + mi * 16 + (mat & 1) * 8 + rr) * RSB + (mat >> 1) * 16);
#pragma unroll
    for (int p = 0; p < 2; p++) {
        uint32_t roff = (uint32_t)((wN * 32 + p * 16 + (mat >> 1) * 8 + rr) * RSB + (mat & 1) * 16);
        bgBase[p] = sbase + OFF_BG + roff;
        buBase[p] = sbase + OFF_BU + roff;
    }

    float cg[2][4][4] = {};
    float cu[2][4][4] = {};

    for (int h0 = 0; h0 < H_DIM; h0 += BK) {
        float4 a0 = *(const float4*)(pA + h0);
        float4 a1 = *(const float4*)(pA + h0 + 4);
        float4 a2 = *(const float4*)(pA + h0 + 8);
        float4 a3 = *(const float4*)(pA + h0 + 12);
        float4 b0 = *(const float4*)(pB + h0);
        float4 b1 = *(const float4*)(pB + h0 + 4);
        float4 b2 = *(const float4*)(pB + h0 + 8);
        float4 b3 = *(const float4*)(pB + h0 + 12);

        __syncthreads();
        uint4 d[2];
        pack16(d, a0, a1, a2, a3);
        *(uint4*)(sm + soA)      = d[0];
        *(uint4*)(sm + soA + 16) = d[1];
        pack16(d, b0, b1, b2, b3);
        *(uint4*)(sm + soB)      = d[0];
        *(uint4*)(sm + soB + 16) = d[1];
        __syncthreads();

#pragma unroll
        for (int ks = 0; ks < 2; ks++) {
            uint32_t af[2][4];
#pragma unroll
            for (int mi = 0; mi < 2; mi++)
                LDM4(af[mi][0], af[mi][1], af[mi][2], af[mi][3], aBase[mi] + ks * 32);
            uint32_t gf[2][4], uf[2][4];
#pragma unroll
            for (int p = 0; p < 2; p++) {
                LDM4(gf[p][0], gf[p][1], gf[p][2], gf[p][3], bgBase[p] + ks * 32);
                LDM4(uf[p][0], uf[p][1], uf[p][2], uf[p][3], buBase[p] + ks * 32);
            }
#pragma unroll
            for (int t = 0; t < 4; t++) {
                int p = t >> 1, q = (t & 1) * 2;
#pragma unroll
                for (int mi = 0; mi < 2; mi++) {
                    mma_f16(cg[mi][t], af[mi][0], af[mi][1], af[mi][2], af[mi][3], gf[p][q], gf[p][q + 1]);
                    mma_f16(cu[mi][t], af[mi][0], af[mi][1], af[mi][2], af[mi][3], uf[p][q], uf[p][q + 1]);
                }
            }
        }
    }

    // ---- epilogue: SiLU(g)*u*w -> g_act (fp16) ----
    int off = g_off[e];
    int g  = lane >> 2;
    int tq = lane & 3;
#pragma unroll
    for (int mi = 0; mi < 2; mi++) {
        int r0 = m0 + wM * 32 + mi * 16 + g;
        int r1 = r0 + 8;
        float w0 = (r0 < n) ? g_list_w[e * T_TOK + r0] : 0.f;
        float w1 = (r1 < n) ? g_list_w[e * T_TOK + r1] : 0.f;
#pragma unroll
        for (int t = 0; t < 4; t++) {
            int col = c0 + wN * 32 + t * 8 + 2 * tq;
            if (r0 < n) {
                float ox = silu_f(cg[mi][t][0]) * cu[mi][t][0] * w0;
                float oy = silu_f(cg[mi][t][1]) * cu[mi][t][1] * w0;
                *(__half2*)&g_act[((size_t)(off + r0)) * I_DIM + col] = __floats2half2_rn(ox, oy);
            }
            if (r1 < n) {
                float ox = silu_f(cg[mi][t][2]) * cu[mi][t][2] * w1;
                float oy = silu_f(cg[mi][t][3]) * cu[mi][t][3] * w1;
                *(__half2*)&g_act[((size_t)(off + r1)) * I_DIM + col] = __floats2half2_rn(ox, oy);
            }
        }
    }
}

// ---------------- grouped down GEMM (fp16 mma m16n8k16) ----------------
__global__ __launch_bounds__(256) void down_kernel(const float* __restrict__ dw) {
    int e  = blockIdx.z;
    int n  = g_cnt[e];
    int m0 = blockIdx.x * BM;
    if (m0 >= n) return;
    int c0  = blockIdx.y * BN;
    int off = g_off[e];

    __shared__ __align__(16) unsigned char sm[(BM + BN) * RSB];
    const uint32_t OFF_B = BM * RSB;
    uint32_t sbase = smem_u32(sm);

    int tid  = threadIdx.x;
    int lane = tid & 31;
    int warp = tid >> 5;
    int wM = warp & 3;
    int wN = warp >> 2;

    // A loader: 2 thr/row, fp16 source (32 B per thread per slab)
    int lr = tid >> 1;
    int hf = tid & 1;
    const __half* pA = g_act + (size_t)(off + min(m0 + lr, n - 1)) * I_DIM + hf * 16;
    uint32_t soA = lr * RSB + hf * 32;

    // B loader: 4 thr/row, fp32 source (8 floats -> 16 B per thread per slab)
    int br = tid >> 2;      // 0..63
    int bq = tid & 3;       // quarter of row (8 floats)
    const float* pB = dw + ((size_t)e * H_DIM + (c0 + br)) * I_DIM + bq * 8;
    uint32_t soB = OFF_B + br * RSB + bq * 16;

    int mat = lane >> 3, rr = lane & 7;
    uint32_t aBase[2], bBase[2];
#pragma unroll
    for (int mi = 0; mi < 2; mi++)
        aBase[mi] = sbase + (uint32_t)((wM * 32 + mi * 16 + (mat & 1) * 8 + rr) * RSB + (mat >> 1) * 16);
#pragma unroll
    for (int p = 0; p < 2; p++)
        bBase[p] = sbase + OFF_B + (uint32_t)((wN * 32 + p * 16 + (mat >> 1) * 8 + rr) * RSB + (mat & 1) * 16);

    float c[2][4][4] = {};

    for (int k0 = 0; k0 < I_DIM; k0 += BK) {
        uint4 va0 = *(const uint4*)(pA + k0);
        uint4 va1 = *(const uint4*)(pA + k0 + 8);
        float4 vb0 = *(const float4*)(pB + k0);
        float4 vb1 = *(const float4*)(pB + k0 + 4);

        __syncthreads();
        *(uint4*)(sm + soA)      = va0;
        *(uint4*)(sm + soA + 16) = va1;
        __half2 hb[4];
        hb[0] = __floats2half2_rn(vb0.x, vb0.y); hb[1] = __floats2half2_rn(vb0.z, vb0.w);
        hb[2] = __floats2half2_rn(vb1.x, vb1.y); hb[3] = __floats2half2_rn(vb1.z, vb1.w);
        *(uint4*)(sm + soB) = *(uint4*)hb;
        __syncthreads();

#pragma unroll
        for (int ks = 0; ks < 2; ks++) {
            uint32_t af[2][4];
#pragma unroll
            for (int mi = 0; mi < 2; mi++)
                LDM4(af[mi][0], af[mi][1], af[mi][2], af[mi][3], aBase[mi] + ks * 32);
            uint32_t bf[2][4];
#pragma unroll
            for (int p = 0; p < 2; p++)
                LDM4(bf[p][0], bf[p][1], bf[p][2], bf[p][3], bBase[p] + ks * 32);
#pragma unroll
            for (int t = 0; t < 4; t++) {
                int p = t >> 1, q = (t & 1) * 2;
#pragma unroll
                for (int mi = 0; mi < 2; mi++)
                    mma_f16(c[mi][t], af[mi][0], af[mi][1], af[mi][2], af[mi][3], bf[p][q], bf[p][q + 1]);
            }
        }
    }

    int g  = lane >> 2;
    int tq = lane & 3;
#pragma unroll
    for (int mi = 0; mi < 2; mi++) {
        int r0 = m0 + wM * 32 + mi * 16 + g;
        int r1 = r0 + 8;
#pragma unroll
        for (int t = 0; t < 4; t++) {
            int col = c0 + wN * 32 + t * 8 + 2 * tq;
            if (r0 < n) {
                float2 o = make_float2(c[mi][t][0], c[mi][t][1]);
                *(float2*)&g_pair[((size_t)(off + r0)) * H_DIM + col] = o;
            }
            if (r1 < n) {
                float2 o = make_float2(c[mi][t][2], c[mi][t][3]);
                *(float2*)&g_pair[((size_t)(off + r1)) * H_DIM + col] = o;
            }
        }
    }
}

// ---------------- per-token reduction ----------------
__global__ void reduce_kernel(float* __restrict__ out) {
    int t = blockIdx.x;
    int s[K_TOP];
#pragma unroll
    for (int k = 0; k < K_TOP; k++) s[k] = g_slot_of[t * K_TOP + k];
    const float4* base = (const float4*)g_pair;
    float4* ob = (float4*)(out + (size_t)t * H_DIM);
    for (int i = threadIdx.x; i < H_DIM / 4; i += blockDim.x) {
        float4 acc = make_float4(0.f, 0.f, 0.f, 0.f);
#pragma unroll
        for (int k = 0; k < K_TOP; k++) {
            float4 v = base[(size_t)s[k] * (H_DIM / 4) + i];
            acc.x += v.x; acc.y += v.y; acc.z += v.z; acc.w += v.w;
        }
        ob[i] = acc;
    }
}

// ---------------- launch ----------------
extern "C" void kernel_launch(void* const* d_in, const int* in_sizes, int n_in,
                              void* d_out, int out_size) {
    const float* x      = (const float*)d_in[0];
    const float* gate_w = (const float*)d_in[1];
    const float* gw     = (const float*)d_in[2];
    const float* uw     = (const float*)d_in[3];
    const float* dw     = (const float*)d_in[4];
    float* out = (float*)d_out;

    float* logits = (out_size >= T_TOK * H_DIM + T_TOK * E_NUM) ? (out + (size_t)T_TOK * H_DIM)
                                                                : (float*)0;

    zero_cnt_kernel<<<1, 32>>>();
    router_kernel<<<T_TOK / 4, 256>>>(x, gate_w, logits);
    scan_kernel<<<1, 32>>>();
    remap_kernel<<<E_NUM, 256>>>();
    gateup_kernel<<<dim3(T_TOK / BM, I_DIM / BN, E_NUM), 256>>>(x, gw, uw);
    down_kernel<<<dim3(T_TOK / BM, H_DIM / BN, E_NUM), 256>>>(dw);
    reduce_kernel<<<T_TOK, 256>>>(out);
}

// round 8
// speedup vs baseline: 1.4594x; 1.3133x over previous
#include <cuda_runtime.h>
#include <cuda_fp16.h>
#include <math.h>
#include <stdint.h>

#define T_TOK 1024
#define H_DIM 2048
#define I_DIM 768
#define E_NUM 32
#define K_TOP 8

#define BM 128
#define BN 64
#define BK 32            // halves per slab (64 B per row)
#define RSB 80           // smem row stride bytes (conflict-free ldmatrix)
#define STAGES 4

#define STG_GU ((BM + 2 * BN) * RSB)   // 20480 B per stage
#define STG_DN ((BM + BN) * RSB)       // 15360 B per stage
#define GU_NC (H_DIM / BK)             // 64
#define DN_NC (I_DIM / BK)             // 24

// ---------------- scratch ----------------
__device__ int    g_cnt[E_NUM];
__device__ int    g_off[E_NUM + 1];
__device__ int    g_list_tok[E_NUM * T_TOK];
__device__ float  g_list_w[E_NUM * T_TOK];
__device__ int    g_list_tk[E_NUM * T_TOK];
__device__ int    g_slot_of[T_TOK * K_TOP];
__device__ __half g_act[(size_t)T_TOK * K_TOP * I_DIM];
__device__ float  g_pair[(size_t)T_TOK * K_TOP * H_DIM];
// fp16 copies of operands
__device__ __half g_xh[(size_t)T_TOK * H_DIM];
__device__ __half g_gwh[(size_t)E_NUM * I_DIM * H_DIM];
__device__ __half g_uwh[(size_t)E_NUM * I_DIM * H_DIM];
__device__ __half g_dwh[(size_t)E_NUM * H_DIM * I_DIM];

__global__ void zero_cnt_kernel() {
    if (threadIdx.x < E_NUM) g_cnt[threadIdx.x] = 0;
}

// ---------------- fp32 -> fp16 streaming convert ----------------
__device__ __forceinline__ void cvt_store(__half* dst, const float4 v) {
    __half2 h[2];
    h[0] = __floats2half2_rn(v.x, v.y);
    h[1] = __floats2half2_rn(v.z, v.w);
    *(uint2*)dst = *(uint2*)h;
}
__global__ void convert_kernel(const float* __restrict__ x,
                               const float* __restrict__ gw,
                               const float* __restrict__ uw,
                               const float* __restrict__ dw) {
    const size_t NX = (size_t)T_TOK * H_DIM / 4;
    const size_t NW = (size_t)E_NUM * I_DIM * H_DIM / 4;
    size_t stride = (size_t)gridDim.x * blockDim.x;
    size_t t0 = (size_t)blockIdx.x * blockDim.x + threadIdx.x;
    for (size_t i = t0; i < NX; i += stride) cvt_store(g_xh  + i * 4, ((const float4*)x)[i]);
    for (size_t i = t0; i < NW; i += stride) cvt_store(g_gwh + i * 4, ((const float4*)gw)[i]);
    for (size_t i = t0; i < NW; i += stride) cvt_store(g_uwh + i * 4, ((const float4*)uw)[i]);
    for (size_t i = t0; i < NW; i += stride) cvt_store(g_dwh + i * 4, ((const float4*)dw)[i]);
}

// ---------------- router ----------------
__global__ void router_kernel(const float* __restrict__ x,
                              const float* __restrict__ gate_w,
                              float* __restrict__ logits_out) {
    const int TPB = 4;
    __shared__ float xs[TPB][H_DIM];
    __shared__ float lg[TPB][E_NUM];

    int t0 = blockIdx.x * TPB;
    const float4* xv  = (const float4*)(x + (size_t)t0 * H_DIM);
    float4*       xsv = (float4*)&xs[0][0];
    for (int i = threadIdx.x; i < TPB * H_DIM / 4; i += blockDim.x) xsv[i] = xv[i];
    __syncthreads();

    int warp = threadIdx.x >> 5;
    int lane = threadIdx.x & 31;

    for (int sub = 0; sub < 4; sub++) {
        int e = warp + sub * 8;
        const float* w = gate_w + (size_t)e * H_DIM;
        float p0 = 0.f, p1 = 0.f, p2 = 0.f, p3 = 0.f;
        for (int h = lane; h < H_DIM; h += 32) {
            float wv = w[h];
            p0 += xs[0][h] * wv;
            p1 += xs[1][h] * wv;
            p2 += xs[2][h] * wv;
            p3 += xs[3][h] * wv;
        }
        for (int o = 16; o; o >>= 1) {
            p0 += __shfl_xor_sync(0xFFFFFFFFu, p0, o);
            p1 += __shfl_xor_sync(0xFFFFFFFFu, p1, o);
            p2 += __shfl_xor_sync(0xFFFFFFFFu, p2, o);
            p3 += __shfl_xor_sync(0xFFFFFFFFu, p3, o);
        }
        if (lane == 0) { lg[0][e] = p0; lg[1][e] = p1; lg[2][e] = p2; lg[3][e] = p3; }
    }
    __syncthreads();

    if (warp < TPB) {
        int t = t0 + warp;
        float logit = lg[warp][lane];
        if (logits_out) logits_out[(size_t)t * E_NUM + lane] = logit;

        float m = logit;
        for (int o = 16; o; o >>= 1) m = fmaxf(m, __shfl_xor_sync(0xFFFFFFFFu, m, o));
        float ex = expf(logit - m);
        float s = ex;
        for (int o = 16; o; o >>= 1) s += __shfl_xor_sync(0xFFFFFFFFu, s, o);
        float prob = ex / s;

        float v = prob;
        float wsum = 0.f;
        float selw[K_TOP];
        int   sele[K_TOP];
#pragma unroll
        for (int k = 0; k < K_TOP; k++) {
            float mv = v;
            for (int o = 16; o; o >>= 1) mv = fmaxf(mv, __shfl_xor_sync(0xFFFFFFFFu, mv, o));
            unsigned msk = __ballot_sync(0xFFFFFFFFu, v == mv);
            int src = __ffs(msk) - 1;
            if (lane == 0) { sele[k] = src; selw[k] = mv; wsum += mv; }
            if (lane == src) v = -1.f;
        }
        if (lane == 0) {
#pragma unroll
            for (int k = 0; k < K_TOP; k++) {
                int e = sele[k];
                float wn = selw[k] / wsum;
                int pos = atomicAdd(&g_cnt[e], 1);
                g_list_tok[e * T_TOK + pos] = t;
                g_list_w[e * T_TOK + pos]   = wn;
                g_list_tk[e * T_TOK + pos]  = t * K_TOP + k;
            }
        }
    }
}

__global__ void scan_kernel() {
    if (threadIdx.x == 0) {
        int acc = 0;
        for (int e = 0; e < E_NUM; e++) { g_off[e] = acc; acc += g_cnt[e]; }
        g_off[E_NUM] = acc;
    }
}

__global__ void remap_kernel() {
    int e = blockIdx.x;
    int n = g_cnt[e], o = g_off[e];
    for (int p = threadIdx.x; p < n; p += blockDim.x)
        g_slot_of[g_list_tk[e * T_TOK + p]] = o + p;
}

__device__ __forceinline__ float silu_f(float g) { return g / (1.f + expf(-g)); }

__device__ __forceinline__ uint32_t smem_u32(const void* p) {
    uint32_t a;
    asm("{ .reg .u64 t; cvta.to.shared.u64 t, %1; cvt.u32.u64 %0, t; }" : "=r"(a) : "l"(p));
    return a;
}

#define LDM4(r0, r1, r2, r3, addr) \
    asm volatile("ldmatrix.sync.aligned.m8n8.x4.shared.b16 {%0,%1,%2,%3}, [%4];" \
                 : "=r"(r0), "=r"(r1), "=r"(r2), "=r"(r3) : "r"(addr))

#define CP16(dst, src) \
    asm volatile("cp.async.cg.shared.global [%0], [%1], 16;" :: "r"(dst), "l"(src) : "memory")
#define CP_COMMIT() asm volatile("cp.async.commit_group;" ::: "memory")
#define CP_WAIT(n)  asm volatile("cp.async.wait_group %0;" :: "n"(n) : "memory")

__device__ __forceinline__ void mma_f16(float* c, uint32_t a0, uint32_t a1, uint32_t a2, uint32_t a3,
                                        uint32_t b0, uint32_t b1) {
    asm volatile("mma.sync.aligned.m16n8k16.row.col.f32.f16.f16.f32 "
                 "{%0,%1,%2,%3}, {%4,%5,%6,%7}, {%8,%9}, {%0,%1,%2,%3};"
                 : "+f"(c[0]), "+f"(c[1]), "+f"(c[2]), "+f"(c[3])
                 : "r"(a0), "r"(a1), "r"(a2), "r"(a3), "r"(b0), "r"(b1));
}

extern __shared__ unsigned char dsm[];

// ---------------- grouped gate+up GEMM (fp16 mma, cp.async 4-stage) ----------------
__global__ __launch_bounds__(256) void gateup_kernel() {
    int e  = blockIdx.z;
    int n  = g_cnt[e];
    int m0 = blockIdx.x * BM;
    if (m0 >= n) return;
    int c0 = blockIdx.y * BN;

    const uint32_t OFF_BG = BM * RSB;
    const uint32_t OFF_BU = (BM + BN) * RSB;
    uint32_t sbase = smem_u32(dsm);

    int tid  = threadIdx.x;
    int lane = tid & 31;
    int warp = tid >> 5;
    int wM = warp & 3;
    int wN = warp >> 2;

    // loader: 2 threads per row, 32 B each
    int lr = tid >> 1;
    int hf = tid & 1;
    int tokA = g_list_tok[e * T_TOK + min(m0 + lr, n - 1)];
    const __half* pA = g_xh + (size_t)tokA * H_DIM + hf * 16;
    uint32_t soA = lr * RSB + hf * 32;
    const __half* pB;
    uint32_t soB;
    if (lr < 64) { pB = g_gwh + ((size_t)e * I_DIM + (c0 + lr)) * H_DIM + hf * 16;      soB = OFF_BG + lr * RSB + hf * 32; }
    else         { pB = g_uwh + ((size_t)e * I_DIM + (c0 + lr - 64)) * H_DIM + hf * 16; soB = OFF_BU + (lr - 64) * RSB + hf * 32; }

    // ldmatrix bases (within stage 0)
    int mat = lane >> 3, rr = lane & 7;
    uint32_t aBase[2], bgBase[2], buBase[2];
#pragma unroll
    for (int mi = 0; mi < 2; mi++)
        aBase[mi] = sbase + (uint32_t)((wM * 32 + mi * 16 + (mat & 1) * 8 + rr) * RSB + (mat >> 1) * 16);
#pragma unroll
    for (int p = 0; p < 2; p++) {
        uint32_t roff = (uint32_t)((wN * 32 + p * 16 + (mat >> 1) * 8 + rr) * RSB + (mat & 1) * 16);
        bgBase[p] = sbase + OFF_BG + roff;
        buBase[p] = sbase + OFF_BU + roff;
    }

    float cg[2][4][4] = {};
    float cu[2][4][4] = {};

    // issue copies for slab i (no commit here)
#define GU_ISSUE(i)                                                     \
    { uint32_t bb = ((i) & (STAGES - 1)) * STG_GU;                      \
      const __half* sa = pA + (i) * 32;                                 \
      CP16(sbase + bb + soA, sa); CP16(sbase + bb + soA + 16, sa + 8);  \
      const __half* sb = pB + (i) * 32;                                 \
      CP16(sbase + bb + soB, sb); CP16(sbase + bb + soB + 16, sb + 8);  \
    }

    GU_ISSUE(0); CP_COMMIT();
    GU_ISSUE(1); CP_COMMIT();
    GU_ISSUE(2); CP_COMMIT();

    for (int i = 0; i < GU_NC; i++) {
        CP_WAIT(STAGES - 2);
        __syncthreads();
        uint32_t st = (i & (STAGES - 1)) * STG_GU;
#pragma unroll
        for (int ks = 0; ks < 2; ks++) {
            uint32_t af[2][4];
#pragma unroll
            for (int mi = 0; mi < 2; mi++)
                LDM4(af[mi][0], af[mi][1], af[mi][2], af[mi][3], aBase[mi] + st + ks * 32);
            uint32_t gf[2][4], uf[2][4];
#pragma unroll
            for (int p = 0; p < 2; p++) {
                LDM4(gf[p][0], gf[p][1], gf[p][2], gf[p][3], bgBase[p] + st + ks * 32);
                LDM4(uf[p][0], uf[p][1], uf[p][2], uf[p][3], buBase[p] + st + ks * 32);
            }
#pragma unroll
            for (int t = 0; t < 4; t++) {
                int p = t >> 1, q = (t & 1) * 2;
#pragma unroll
                for (int mi = 0; mi < 2; mi++) {
                    mma_f16(cg[mi][t], af[mi][0], af[mi][1], af[mi][2], af[mi][3], gf[p][q], gf[p][q + 1]);
                    mma_f16(cu[mi][t], af[mi][0], af[mi][1], af[mi][2], af[mi][3], uf[p][q], uf[p][q + 1]);
                }
            }
        }
        // ALWAYS commit (possibly empty) so wait_group(2) at top of iter j
        // always has the last two groups == iters j-1, j-2 -> stage j is safe,
        // including the pipeline tail.
        if (i + STAGES - 1 < GU_NC) GU_ISSUE(i + STAGES - 1);
        CP_COMMIT();
    }
#undef GU_ISSUE

    // ---- epilogue ----
    int off = g_off[e];
    int g  = lane >> 2;
    int tq = lane & 3;
#pragma unroll
    for (int mi = 0; mi < 2; mi++) {
        int r0 = m0 + wM * 32 + mi * 16 + g;
        int r1 = r0 + 8;
        float w0 = (r0 < n) ? g_list_w[e * T_TOK + r0] : 0.f;
        float w1 = (r1 < n) ? g_list_w[e * T_TOK + r1] : 0.f;
#pragma unroll
        for (int t = 0; t < 4; t++) {
            int col = c0 + wN * 32 + t * 8 + 2 * tq;
            if (r0 < n) {
                float ox = silu_f(cg[mi][t][0]) * cu[mi][t][0] * w0;
                float oy = silu_f(cg[mi][t][1]) * cu[mi][t][1] * w0;
                *(__half2*)&g_act[((size_t)(off + r0)) * I_DIM + col] = __floats2half2_rn(ox, oy);
            }
            if (r1 < n) {
                float ox = silu_f(cg[mi][t][2]) * cu[mi][t][2] * w1;
                float oy = silu_f(cg[mi][t][3]) * cu[mi][t][3] * w1;
                *(__half2*)&g_act[((size_t)(off + r1)) * I_DIM + col] = __floats2half2_rn(ox, oy);
            }
        }
    }
}

// ---------------- grouped down GEMM (fp16 mma, cp.async 4-stage) ----------------
__global__ __launch_bounds__(256) void down_kernel() {
    int e  = blockIdx.z;
    int n  = g_cnt[e];
    int m0 = blockIdx.x * BM;
    if (m0 >= n) return;
    int c0  = blockIdx.y * BN;
    int off = g_off[e];

    const uint32_t OFF_B = BM * RSB;
    uint32_t sbase = smem_u32(dsm);

    int tid  = threadIdx.x;
    int lane = tid & 31;
    int warp = tid >> 5;
    int wM = warp & 3;
    int wN = warp >> 2;

    // A loader: 2 thr/row (128 rows)
    int lr = tid >> 1;
    int hf = tid & 1;
    const __half* pA = g_act + (size_t)(off + min(m0 + lr, n - 1)) * I_DIM + hf * 16;
    uint32_t soA = lr * RSB + hf * 32;
    // B loader: threads 0..127, 2 thr/row (64 rows)
    const __half* pB = 0;
    uint32_t soB = 0;
    if (tid < 128) {
        int br = tid >> 1, bh = tid & 1;
        pB = g_dwh + ((size_t)e * H_DIM + (c0 + br)) * I_DIM + bh * 16;
        soB = OFF_B + br * RSB + bh * 32;
    }

    int mat = lane >> 3, rr = lane & 7;
    uint32_t aBase[2], bBase[2];
#pragma unroll
    for (int mi = 0; mi < 2; mi++)
        aBase[mi] = sbase + (uint32_t)((wM * 32 + mi * 16 + (mat & 1) * 8 + rr) * RSB + (mat >> 1) * 16);
#pragma unroll
    for (int p = 0; p < 2; p++)
        bBase[p] = sbase + OFF_B + (uint32_t)((wN * 32 + p * 16 + (mat >> 1) * 8 + rr) * RSB + (mat & 1) * 16);

    float c[2][4][4] = {};

#define DN_ISSUE(i)                                                      \
    { uint32_t bb = ((i) & (STAGES - 1)) * STG_DN;                       \
      const __half* sa = pA + (i) * 32;                                  \
      CP16(sbase + bb + soA, sa); CP16(sbase + bb + soA + 16, sa + 8);   \
      if (tid < 128) {                                                   \
          const __half* sb = pB + (i) * 32;                              \
          CP16(sbase + bb + soB, sb); CP16(sbase + bb + soB + 16, sb + 8); } \
    }

    DN_ISSUE(0); CP_COMMIT();
    DN_ISSUE(1); CP_COMMIT();
    DN_ISSUE(2); CP_COMMIT();

    for (int i = 0; i < DN_NC; i++) {
        CP_WAIT(STAGES - 2);
        __syncthreads();
        uint32_t st = (i & (STAGES - 1)) * STG_DN;
#pragma unroll
        for (int ks = 0; ks < 2; ks++) {
            uint32_t af[2][4];
#pragma unroll
            for (int mi = 0; mi < 2; mi++)
                LDM4(af[mi][0], af[mi][1], af[mi][2], af[mi][3], aBase[mi] + st + ks * 32);
            uint32_t bf[2][4];
#pragma unroll
            for (int p = 0; p < 2; p++)
                LDM4(bf[p][0], bf[p][1], bf[p][2], bf[p][3], bBase[p] + st + ks * 32);
#pragma unroll
            for (int t = 0; t < 4; t++) {
                int p = t >> 1, q = (t & 1) * 2;
#pragma unroll
                for (int mi = 0; mi < 2; mi++)
                    mma_f16(c[mi][t], af[mi][0], af[mi][1], af[mi][2], af[mi][3], bf[p][q], bf[p][q + 1]);
            }
        }
        // tail-safe: unconditional commit (see gateup comment)
        if (i + STAGES - 1 < DN_NC) DN_ISSUE(i + STAGES - 1);
        CP_COMMIT();
    }
#undef DN_ISSUE

    int g  = lane >> 2;
    int tq = lane & 3;
#pragma unroll
    for (int mi = 0; mi < 2; mi++) {
        int r0 = m0 + wM * 32 + mi * 16 + g;
        int r1 = r0 + 8;
#pragma unroll
        for (int t = 0; t < 4; t++) {
            int col = c0 + wN * 32 + t * 8 + 2 * tq;
            if (r0 < n) {
                float2 o = make_float2(c[mi][t][0], c[mi][t][1]);
                *(float2*)&g_pair[((size_t)(off + r0)) * H_DIM + col] = o;
            }
            if (r1 < n) {
                float2 o = make_float2(c[mi][t][2], c[mi][t][3]);
                *(float2*)&g_pair[((size_t)(off + r1)) * H_DIM + col] = o;
            }
        }
    }
}

// ---------------- per-token reduction ----------------
__global__ void reduce_kernel(float* __restrict__ out) {
    int t = blockIdx.x;
    int s[K_TOP];
#pragma unroll
    for (int k = 0; k < K_TOP; k++) s[k] = g_slot_of[t * K_TOP + k];
    const float4* base = (const float4*)g_pair;
    float4* ob = (float4*)(out + (size_t)t * H_DIM);
    for (int i = threadIdx.x; i < H_DIM / 4; i += blockDim.x) {
        float4 acc = make_float4(0.f, 0.f, 0.f, 0.f);
#pragma unroll
        for (int k = 0; k < K_TOP; k++) {
            float4 v = base[(size_t)s[k] * (H_DIM / 4) + i];
            acc.x += v.x; acc.y += v.y; acc.z += v.z; acc.w += v.w;
        }
        ob[i] = acc;
    }
}

// ---------------- launch ----------------
extern "C" void kernel_launch(void* const* d_in, const int* in_sizes, int n_in,
                              void* d_out, int out_size) {
    const float* x      = (const float*)d_in[0];
    const float* gate_w = (const float*)d_in[1];
    const float* gw     = (const float*)d_in[2];
    const float* uw     = (const float*)d_in[3];
    const float* dw     = (const float*)d_in[4];
    float* out = (float*)d_out;

    float* logits = (out_size >= T_TOK * H_DIM + T_TOK * E_NUM) ? (out + (size_t)T_TOK * H_DIM)
                                                                : (float*)0;

    cudaFuncSetAttribute(gateup_kernel, cudaFuncAttributeMaxDynamicSharedMemorySize,
                         STAGES * STG_GU);
    cudaFuncSetAttribute(down_kernel, cudaFuncAttributeMaxDynamicSharedMemorySize,
                         STAGES * STG_DN);

    zero_cnt_kernel<<<1, 32>>>();
    convert_kernel<<<2048, 256>>>(x, gw, uw, dw);
    router_kernel<<<T_TOK / 4, 256>>>(x, gate_w, logits);
    scan_kernel<<<1, 32>>>();
    remap_kernel<<<E_NUM, 256>>>();
    gateup_kernel<<<dim3(T_TOK / BM, I_DIM / BN, E_NUM), 256, STAGES * STG_GU>>>();
    down_kernel<<<dim3(T_TOK / BM, H_DIM / BN, E_NUM), 256, STAGES * STG_DN>>>();
    reduce_kernel<<<T_TOK, 256>>>(out);
}